// round 1
// baseline (speedup 1.0000x reference)
#include <cuda_runtime.h>
#include <math.h>

// Problem constants
#define BSZ   2
#define TLEN  2048
#define DM    1024
#define DI    2048
#define NST   16
#define DTR   64
#define NPROJ 96            // DTR + 2*NST
#define MROWS (BSZ*TLEN)    // 4096

// Scratch (device globals: allocation-free rule)
__device__ float g_u[(size_t)MROWS*DI];
__device__ float g_z[(size_t)MROWS*DI];
__device__ float g_uc[(size_t)MROWS*DI];
__device__ float g_proj[(size_t)MROWS*NPROJ];
__device__ float g_delta[(size_t)MROWS*DI];
__device__ float g_y[(size_t)MROWS*DI];

// ---------------------------------------------------------------------------
// Generic fp32 SGEMM: C[M,N] = A[M,K](lda) * B[K,N](ldb), row-major.
// 128x128 block tile, BK=8, 256 threads, 8x8 per thread.
// Requires K % 8 == 0, lda/ldb/ldc % 4 == 0, M % 128 == 0 (true here).
// N may be arbitrary (guards on B loads + C stores).
// ---------------------------------------------------------------------------
__global__ __launch_bounds__(256) void sgemm128(
    const float* __restrict__ A, const float* __restrict__ B,
    float* __restrict__ C, int M, int N, int K, int lda, int ldb, int ldc)
{
    __shared__ float As[8][128];
    __shared__ float Bs[8][128];

    const int tid = threadIdx.x;
    const int tx = tid & 15;          // 0..15 (N direction)
    const int ty = tid >> 4;          // 0..15 (M direction)
    const int row0 = blockIdx.y * 128;
    const int col0 = blockIdx.x * 128;

    // A-tile load map: 128 rows x 8 k, float4 per thread
    const int a_row = tid >> 1;           // 0..127
    const int a_col = (tid & 1) * 4;      // 0 or 4
    // B-tile load map: 8 k-rows x 128 cols, float4 per thread
    const int b_row = tid >> 5;           // 0..7
    const int b_col = (tid & 31) * 4;     // 0..124

    float acc[8][8];
#pragma unroll
    for (int i = 0; i < 8; i++)
#pragma unroll
        for (int j = 0; j < 8; j++) acc[i][j] = 0.f;

    for (int k0 = 0; k0 < K; k0 += 8) {
        // Load A tile (transposed into As[k][m])
        {
            const int gr = row0 + a_row;
            float4 v = *(const float4*)(A + (size_t)gr * lda + k0 + a_col);
            As[a_col + 0][a_row] = v.x;
            As[a_col + 1][a_row] = v.y;
            As[a_col + 2][a_row] = v.z;
            As[a_col + 3][a_row] = v.w;
        }
        // Load B tile
        {
            const int gc = col0 + b_col;
            const float* bp = B + (size_t)(k0 + b_row) * ldb;
            float4 v;
            if (gc + 3 < N) {
                v = *(const float4*)(bp + gc);
            } else {
                v.x = (gc + 0 < N) ? bp[gc + 0] : 0.f;
                v.y = (gc + 1 < N) ? bp[gc + 1] : 0.f;
                v.z = (gc + 2 < N) ? bp[gc + 2] : 0.f;
                v.w = (gc + 3 < N) ? bp[gc + 3] : 0.f;
            }
            *(float4*)&Bs[b_row][b_col] = v;
        }
        __syncthreads();

#pragma unroll
        for (int kk = 0; kk < 8; kk++) {
            float ar[8], br[8];
            *(float4*)&ar[0] = *(const float4*)&As[kk][ty * 8];
            *(float4*)&ar[4] = *(const float4*)&As[kk][ty * 8 + 4];
            *(float4*)&br[0] = *(const float4*)&Bs[kk][tx * 8];
            *(float4*)&br[4] = *(const float4*)&Bs[kk][tx * 8 + 4];
#pragma unroll
            for (int i = 0; i < 8; i++)
#pragma unroll
                for (int j = 0; j < 8; j++) acc[i][j] += ar[i] * br[j];
        }
        __syncthreads();
    }

#pragma unroll
    for (int i = 0; i < 8; i++) {
        const int row = row0 + ty * 8 + i;
#pragma unroll
        for (int j = 0; j < 8; j++) {
            const int col = col0 + tx * 8 + j;
            if (col < N) C[(size_t)row * ldc + col] = acc[i][j];
        }
    }
}

// ---------------------------------------------------------------------------
// Causal depthwise conv1d (k=4) + SiLU:  uc = silu(conv_b + sum_k u[t-3+k]*w[k])
// ---------------------------------------------------------------------------
__global__ void conv_silu_kernel(const float* __restrict__ cw,
                                 const float* __restrict__ cb)
{
    const size_t idx = (size_t)blockIdx.x * blockDim.x + threadIdx.x;
    if (idx >= (size_t)MROWS * DI) return;
    const int d = (int)(idx % DI);
    const int m = (int)(idx / DI);
    const int t = m % TLEN;

    float acc = cb[d];
#pragma unroll
    for (int k = 0; k < 4; k++) {
        const int tt = t - 3 + k;
        if (tt >= 0)
            acc += g_u[(size_t)(m - 3 + k) * DI + d] * cw[d * 4 + k];
    }
    // SiLU
    g_uc[idx] = acc / (1.f + __expf(-acc));
}

// ---------------------------------------------------------------------------
// delta = softplus(proj[:, :64] @ W_dt + b_dt)   (K=64, fused epilogue)
// Block: 256 threads over d, 8 rows of m per block.
// ---------------------------------------------------------------------------
#define DT_TM 8
__global__ __launch_bounds__(256) void dt_softplus_kernel(
    const float* __restrict__ W_dt, const float* __restrict__ b_dt)
{
    __shared__ float sp[DT_TM][DTR];
    const int m0 = blockIdx.y * DT_TM;
    const int d = blockIdx.x * 256 + threadIdx.x;

    for (int i = threadIdx.x; i < DT_TM * DTR; i += 256)
        sp[i / DTR][i % DTR] = g_proj[(size_t)(m0 + i / DTR) * NPROJ + (i % DTR)];
    __syncthreads();

    const float bb = b_dt[d];
    float acc[DT_TM];
#pragma unroll
    for (int i = 0; i < DT_TM; i++) acc[i] = bb;

#pragma unroll 8
    for (int r = 0; r < DTR; r++) {
        const float w = W_dt[(size_t)r * DI + d];
#pragma unroll
        for (int i = 0; i < DT_TM; i++) acc[i] += sp[i][r] * w;
    }

#pragma unroll
    for (int i = 0; i < DT_TM; i++) {
        const float x = acc[i];
        // softplus = max(x,0) + log1p(exp(-|x|))
        const float spv = fmaxf(x, 0.f) + log1pf(__expf(-fabsf(x)));
        g_delta[(size_t)(m0 + i) * DI + d] = spv;
    }
}

// ---------------------------------------------------------------------------
// Sequential SSM scan. One thread per (b, d). 128 d per block, grid (DI/128, B).
// h[n] = exp(delta*A[n])*h[n] + delta*uc*B_t[n];  y_t = sum_n h[n]*C_t[n]
// y = (y + uc*D) * silu(z)
// ---------------------------------------------------------------------------
__global__ __launch_bounds__(128) void scan_kernel(
    const float* __restrict__ A_log, const float* __restrict__ Dp)
{
    const int b = blockIdx.y;
    const int d = blockIdx.x * 128 + threadIdx.x;

    float Aexp[NST];
#pragma unroll
    for (int n = 0; n < NST; n++)
        Aexp[n] = -__expf(A_log[(size_t)d * NST + n]);
    const float Dd = Dp[d];

    float h[NST];
#pragma unroll
    for (int n = 0; n < NST; n++) h[n] = 0.f;

    __shared__ float sBC[2 * NST];   // [0..15] = B_t, [16..31] = C_t
    const float* proj_b = g_proj + (size_t)b * TLEN * NPROJ;

    for (int t = 0; t < TLEN; t++) {
        if (threadIdx.x < 2 * NST)
            sBC[threadIdx.x] = proj_b[(size_t)t * NPROJ + DTR + threadIdx.x];
        __syncthreads();

        const size_t idx = ((size_t)b * TLEN + t) * DI + d;
        const float delta = g_delta[idx];
        const float uc = g_uc[idx];
        const float du = delta * uc;

        float y = 0.f;
#pragma unroll
        for (int n = 0; n < NST; n++) {
            h[n] = __expf(delta * Aexp[n]) * h[n] + du * sBC[n];
            y += h[n] * sBC[NST + n];
        }

        const float z = g_z[idx];
        const float gate = z / (1.f + __expf(-z));
        g_y[idx] = (y + uc * Dd) * gate;
        __syncthreads();
    }
}

// ---------------------------------------------------------------------------
extern "C" void kernel_launch(void* const* d_in, const int* in_sizes, int n_in,
                              void* d_out, int out_size)
{
    const float* x      = (const float*)d_in[0];  // (B,T,DM)
    const float* W_in   = (const float*)d_in[1];  // (DM, 2*DI)
    const float* conv_w = (const float*)d_in[2];  // (DI,4)
    const float* conv_b = (const float*)d_in[3];  // (DI)
    const float* W_xprj = (const float*)d_in[4];  // (DI, 96)
    const float* W_dt   = (const float*)d_in[5];  // (64, DI)
    const float* b_dt   = (const float*)d_in[6];  // (DI)
    const float* A_log  = (const float*)d_in[7];  // (DI,16)
    const float* Dp     = (const float*)d_in[8];  // (DI)
    const float* W_out  = (const float*)d_in[9];  // (DI, DM)
    float* out = (float*)d_out;

    void *pu, *pz, *puc, *pproj, *py;
    cudaGetSymbolAddress(&pu, g_u);
    cudaGetSymbolAddress(&pz, g_z);
    cudaGetSymbolAddress(&puc, g_uc);
    cudaGetSymbolAddress(&pproj, g_proj);
    cudaGetSymbolAddress(&py, g_y);

    // 1) xz = x @ W_in  -> u (cols 0..DI-1), z (cols DI..2DI-1)
    {
        dim3 grid(DI / 128, MROWS / 128);
        sgemm128<<<grid, 256>>>(x, W_in,       (float*)pu, MROWS, DI, DM, DM, 2 * DI, DI);
        sgemm128<<<grid, 256>>>(x, W_in + DI,  (float*)pz, MROWS, DI, DM, DM, 2 * DI, DI);
    }

    // 2) causal depthwise conv + SiLU
    {
        const size_t total = (size_t)MROWS * DI;
        conv_silu_kernel<<<(unsigned)((total + 255) / 256), 256>>>(conv_w, conv_b);
    }

    // 3) proj = uc @ W_xproj   (N = 96)
    {
        dim3 grid(1, MROWS / 128);
        sgemm128<<<grid, 256>>>((const float*)puc, W_xprj, (float*)pproj,
                                MROWS, NPROJ, DI, DI, NPROJ, NPROJ);
    }

    // 4) delta = softplus(dt @ W_dt + b_dt)
    {
        dim3 grid(DI / 256, MROWS / DT_TM);
        dt_softplus_kernel<<<grid, 256>>>(W_dt, b_dt);
    }

    // 5) SSM scan + skip + gate
    {
        dim3 grid(DI / 128, BSZ);
        scan_kernel<<<grid, 128>>>(A_log, Dp);
    }

    // 6) out = y @ W_out
    {
        dim3 grid(DM / 128, MROWS / 128);
        sgemm128<<<grid, 256>>>((const float*)py, W_out, out,
                                MROWS, DM, DI, DI, DM, DM);
    }
}

// round 3
// speedup vs baseline: 1.3379x; 1.3379x over previous
#include <cuda_runtime.h>
#include <cuda_bf16.h>
#include <cstdint>
#include <math.h>

// Problem constants
#define BSZ   2
#define TLEN  2048
#define DM    1024
#define DI    2048
#define NST   16
#define DTR   64
#define NPROJ 96
#define MROWS (BSZ*TLEN)    // 4096

// ---------------------------------------------------------------------------
// Scratch (device globals; allocation-free rule)
// ---------------------------------------------------------------------------
__device__ __align__(256) float g_uz[(size_t)MROWS * 2 * DI];   // u | z
__device__ __align__(256) float g_uc[(size_t)MROWS * DI];
__device__ __align__(256) float g_proj[(size_t)MROWS * NPROJ];
__device__ __align__(256) float g_delta[(size_t)MROWS * DI];

__device__ __align__(256) __nv_bfloat16 gx_h[(size_t)MROWS * DM];
__device__ __align__(256) __nv_bfloat16 gx_l[(size_t)MROWS * DM];
__device__ __align__(256) __nv_bfloat16 gWinT_h[(size_t)(2 * DI) * DM];
__device__ __align__(256) __nv_bfloat16 gWinT_l[(size_t)(2 * DI) * DM];
__device__ __align__(256) __nv_bfloat16 guc_h[(size_t)MROWS * DI];
__device__ __align__(256) __nv_bfloat16 guc_l[(size_t)MROWS * DI];
__device__ __align__(256) __nv_bfloat16 gWxT_h[(size_t)NPROJ * DI];
__device__ __align__(256) __nv_bfloat16 gWxT_l[(size_t)NPROJ * DI];
__device__ __align__(256) __nv_bfloat16 gy_h[(size_t)MROWS * DI];
__device__ __align__(256) __nv_bfloat16 gy_l[(size_t)MROWS * DI];
__device__ __align__(256) __nv_bfloat16 gWoT_h[(size_t)DM * DI];
__device__ __align__(256) __nv_bfloat16 gWoT_l[(size_t)DM * DI];

// ---------------------------------------------------------------------------
// PTX helpers (baseline sm_90 features only — NO tcgen05, bench targets sm_103)
// ---------------------------------------------------------------------------
__device__ __forceinline__ uint32_t smem_u32(const void* p) {
    uint32_t a;
    asm("{ .reg .u64 t; cvta.to.shared.u64 t, %1; cvt.u32.u64 %0, t; }"
        : "=r"(a) : "l"(p));
    return a;
}
__device__ __forceinline__ void cp_async16(uint32_t dst, const void* src) {
    asm volatile("cp.async.cg.shared.global [%0], [%1], 16;" :: "r"(dst), "l"(src));
}
#define CP_COMMIT() asm volatile("cp.async.commit_group;" ::: "memory")
#define CP_WAIT(n)  asm volatile("cp.async.wait_group %0;" :: "n"(n) : "memory")

__device__ __forceinline__ void mma16816(float* c, const uint32_t* a, const uint32_t* b) {
    asm volatile(
        "mma.sync.aligned.m16n8k16.row.col.f32.bf16.bf16.f32 "
        "{%0,%1,%2,%3}, {%4,%5,%6,%7}, {%8,%9}, {%0,%1,%2,%3};"
        : "+f"(c[0]), "+f"(c[1]), "+f"(c[2]), "+f"(c[3])
        : "r"(a[0]), "r"(a[1]), "r"(a[2]), "r"(a[3]), "r"(b[0]), "r"(b[1]));
}

// ---------------------------------------------------------------------------
// bf16 3-split HMMA GEMM:  C[M,N] = A[M,K] * B^T   (B stored [N,K] row-major)
// A = Ah+Al, B = Bh+Bl; compute AhBh + AlBh + AhBl into fp32 accumulators.
// CTA tile 128 x BN (BN = 128 or 96), BK = 32, 256 threads (8 warps, 4x2),
// warp tile 32 x BN/2. cp.async double-buffered smem, padded stride 40.
// ---------------------------------------------------------------------------
#define BKP 40                       // padded K stride in bf16 elements
#define TILE_ELS (128 * BKP)         // 5120 els per operand tile
#define STAGE_ELS (4 * TILE_ELS)     // Ah, Al, Bh, Bl
#define TG_SMEM_BYTES (2 * STAGE_ELS * 2)   // 81920 bytes

__device__ __forceinline__ void tile_load(const __nv_bfloat16* __restrict__ src,
                                          int row0, int K, int k0,
                                          uint32_t sbase, int tid, int nrows) {
#pragma unroll
    for (int p = 0; p < 2; ++p) {
        const int idx = tid + p * 256;
        const int row = idx >> 2;
        const int seg = idx & 3;
        if (row < nrows)
            cp_async16(sbase + (uint32_t)(row * BKP + seg * 8) * 2,
                       src + (size_t)(row0 + row) * K + k0 + seg * 8);
    }
}

template <int BN>
__global__ __launch_bounds__(256, 2) void tgemm_mma(
    const __nv_bfloat16* __restrict__ Ah, const __nv_bfloat16* __restrict__ Al,
    const __nv_bfloat16* __restrict__ Bh, const __nv_bfloat16* __restrict__ Bl,
    float* __restrict__ C, int K, int ldc)
{
    extern __shared__ __nv_bfloat16 sm[];
    const uint32_t smb = smem_u32(sm);
    const int tid = threadIdx.x;
    const int wid = tid >> 5, lane = tid & 31;
    const int wy = wid & 3, wx = wid >> 2;       // 4 (M) x 2 (N)
    const int g = lane >> 2, q2 = (lane & 3) * 2;
    const int m0 = blockIdx.y * 128;
    const int n0 = blockIdx.x * BN;
    constexpr int WN = BN / 2;                   // 64 or 48
    constexpr int NI = WN / 8;                   // 8 or 6
    constexpr int BROWS = (BN < 128) ? BN : 128;

    float acc[2][NI][4];
#pragma unroll
    for (int mi = 0; mi < 2; ++mi)
#pragma unroll
        for (int ni = 0; ni < NI; ++ni)
#pragma unroll
            for (int j = 0; j < 4; ++j) acc[mi][ni][j] = 0.f;

    const int nc = K >> 5;

    // prologue: stage 0
    {
        const uint32_t sb = smb;
        tile_load(Ah, m0, K, 0, sb,                     tid, 128);
        tile_load(Al, m0, K, 0, sb + TILE_ELS * 2,      tid, 128);
        tile_load(Bh, n0, K, 0, sb + 2 * TILE_ELS * 2,  tid, BROWS);
        tile_load(Bl, n0, K, 0, sb + 3 * TILE_ELS * 2,  tid, BROWS);
        CP_COMMIT();
    }

    for (int c = 0; c < nc; ++c) {
        const int s = c & 1;
        if (c + 1 < nc) {
            const int k0 = (c + 1) << 5;
            const uint32_t sb = smb + (uint32_t)(s ^ 1) * STAGE_ELS * 2;
            tile_load(Ah, m0, K, k0, sb,                    tid, 128);
            tile_load(Al, m0, K, k0, sb + TILE_ELS * 2,     tid, 128);
            tile_load(Bh, n0, K, k0, sb + 2 * TILE_ELS * 2, tid, BROWS);
            tile_load(Bl, n0, K, k0, sb + 3 * TILE_ELS * 2, tid, BROWS);
            CP_COMMIT();
            CP_WAIT(1);
        } else {
            CP_WAIT(0);
        }
        __syncthreads();

        const __nv_bfloat16* Ash = sm + (size_t)s * STAGE_ELS;
        const __nv_bfloat16* Asl = Ash + TILE_ELS;
        const __nv_bfloat16* Bsh = Asl + TILE_ELS;
        const __nv_bfloat16* Bsl = Bsh + TILE_ELS;

#pragma unroll
        for (int kk = 0; kk < 2; ++kk) {
            const int kc = kk * 16;
            uint32_t ah[2][4], al[2][4];
#pragma unroll
            for (int mi = 0; mi < 2; ++mi) {
                const int r0 = wy * 32 + mi * 16;
                ah[mi][0] = *(const uint32_t*)&Ash[(r0 + g) * BKP + kc + q2];
                ah[mi][1] = *(const uint32_t*)&Ash[(r0 + g + 8) * BKP + kc + q2];
                ah[mi][2] = *(const uint32_t*)&Ash[(r0 + g) * BKP + kc + 8 + q2];
                ah[mi][3] = *(const uint32_t*)&Ash[(r0 + g + 8) * BKP + kc + 8 + q2];
                al[mi][0] = *(const uint32_t*)&Asl[(r0 + g) * BKP + kc + q2];
                al[mi][1] = *(const uint32_t*)&Asl[(r0 + g + 8) * BKP + kc + q2];
                al[mi][2] = *(const uint32_t*)&Asl[(r0 + g) * BKP + kc + 8 + q2];
                al[mi][3] = *(const uint32_t*)&Asl[(r0 + g + 8) * BKP + kc + 8 + q2];
            }
#pragma unroll
            for (int ni = 0; ni < NI; ++ni) {
                const int nb = wx * WN + ni * 8;
                uint32_t bh[2], bl[2];
                bh[0] = *(const uint32_t*)&Bsh[(nb + g) * BKP + kc + q2];
                bh[1] = *(const uint32_t*)&Bsh[(nb + g) * BKP + kc + 8 + q2];
                bl[0] = *(const uint32_t*)&Bsl[(nb + g) * BKP + kc + q2];
                bl[1] = *(const uint32_t*)&Bsl[(nb + g) * BKP + kc + 8 + q2];
#pragma unroll
                for (int mi = 0; mi < 2; ++mi) {
                    mma16816(acc[mi][ni], ah[mi], bh);
                    mma16816(acc[mi][ni], al[mi], bh);
                    mma16816(acc[mi][ni], ah[mi], bl);
                }
            }
        }
        __syncthreads();
    }

    // epilogue
#pragma unroll
    for (int mi = 0; mi < 2; ++mi) {
        const int row = m0 + wy * 32 + mi * 16 + g;
#pragma unroll
        for (int ni = 0; ni < NI; ++ni) {
            const int col = n0 + wx * WN + ni * 8 + q2;
            *(float2*)&C[(size_t)row * ldc + col] =
                make_float2(acc[mi][ni][0], acc[mi][ni][1]);
            *(float2*)&C[(size_t)(row + 8) * ldc + col] =
                make_float2(acc[mi][ni][2], acc[mi][ni][3]);
        }
    }
}

// ---------------------------------------------------------------------------
// fp32 -> bf16 hi/lo split (x only; conv & scan fuse their own splits)
// ---------------------------------------------------------------------------
__global__ void split_kernel(const float* __restrict__ src,
                             __nv_bfloat16* __restrict__ hi,
                             __nv_bfloat16* __restrict__ lo, size_t n)
{
    size_t i = (size_t)blockIdx.x * blockDim.x + threadIdx.x;
    if (i >= n) return;
    float v = src[i];
    __nv_bfloat16 h = __float2bfloat16(v);
    hi[i] = h;
    lo[i] = __float2bfloat16(v - __bfloat162float(h));
}

// ---------------------------------------------------------------------------
// transpose + split: src [K][N] fp32 -> hi/lo [N][K] bf16  (K,N mult of 32)
// ---------------------------------------------------------------------------
__global__ __launch_bounds__(1024) void tsplit_kernel(
    const float* __restrict__ src, __nv_bfloat16* __restrict__ hi,
    __nv_bfloat16* __restrict__ lo, int K, int N)
{
    __shared__ float tile[32][33];
    const int n0 = blockIdx.x * 32, k0 = blockIdx.y * 32;
    const int tx = threadIdx.x & 31, ty = threadIdx.x >> 5;
    tile[ty][tx] = src[(size_t)(k0 + ty) * N + n0 + tx];
    __syncthreads();
    const int k = k0 + tx, n = n0 + ty;
    float v = tile[tx][ty];
    __nv_bfloat16 h = __float2bfloat16(v);
    hi[(size_t)n * K + k] = h;
    lo[(size_t)n * K + k] = __float2bfloat16(v - __bfloat162float(h));
}

// ---------------------------------------------------------------------------
// Causal depthwise conv1d (k=4) + SiLU; writes fp32 uc AND bf16 hi/lo split
// ---------------------------------------------------------------------------
__global__ void conv_silu_kernel(const float* __restrict__ cw,
                                 const float* __restrict__ cb)
{
    const size_t idx = (size_t)blockIdx.x * blockDim.x + threadIdx.x;
    if (idx >= (size_t)MROWS * DI) return;
    const int d = (int)(idx % DI);
    const int m = (int)(idx / DI);
    const int t = m % TLEN;

    float acc = cb[d];
#pragma unroll
    for (int k = 0; k < 4; k++) {
        const int tt = t - 3 + k;
        if (tt >= 0)
            acc += g_uz[(size_t)(m - 3 + k) * (2 * DI) + d] * cw[d * 4 + k];
    }
    const float v = acc / (1.f + __expf(-acc));
    g_uc[idx] = v;
    const __nv_bfloat16 h = __float2bfloat16(v);
    guc_h[idx] = h;
    guc_l[idx] = __float2bfloat16(v - __bfloat162float(h));
}

// ---------------------------------------------------------------------------
// delta = softplus(proj[:, :64] @ W_dt + b_dt)
// ---------------------------------------------------------------------------
#define DT_TM 8
__global__ __launch_bounds__(256) void dt_softplus_kernel(
    const float* __restrict__ W_dt, const float* __restrict__ b_dt)
{
    __shared__ float sp[DT_TM][DTR];
    const int m0 = blockIdx.y * DT_TM;
    const int d = blockIdx.x * 256 + threadIdx.x;

    for (int i = threadIdx.x; i < DT_TM * DTR; i += 256)
        sp[i / DTR][i % DTR] = g_proj[(size_t)(m0 + i / DTR) * NPROJ + (i % DTR)];
    __syncthreads();

    const float bb = b_dt[d];
    float acc[DT_TM];
#pragma unroll
    for (int i = 0; i < DT_TM; i++) acc[i] = bb;

#pragma unroll 8
    for (int r = 0; r < DTR; r++) {
        const float w = W_dt[(size_t)r * DI + d];
#pragma unroll
        for (int i = 0; i < DT_TM; i++) acc[i] += sp[i][r] * w;
    }
#pragma unroll
    for (int i = 0; i < DT_TM; i++) {
        const float x = acc[i];
        g_delta[(size_t)(m0 + i) * DI + d] =
            fmaxf(x, 0.f) + log1pf(__expf(-fabsf(x)));
    }
}

// ---------------------------------------------------------------------------
// SSM scan: 8 lanes per d (2 states each), warp = 4 d x 8 n-lanes.
// Writes gated output directly as bf16 hi/lo (feeds final GEMM).
// ---------------------------------------------------------------------------
#define SCAN_TB 64
__global__ __launch_bounds__(256) void scan_kernel(
    const float* __restrict__ A_log, const float* __restrict__ Dp)
{
    const int b = blockIdx.y;
    const int tid = threadIdx.x;
    const int warp = tid >> 5;
    const int lane = tid & 31;
    const int d_sub = lane >> 3;
    const int n = lane & 7;
    const int d = blockIdx.x * 32 + warp * 4 + d_sub;

    const float A0 = -__expf(A_log[(size_t)d * NST + n]);
    const float A1 = -__expf(A_log[(size_t)d * NST + n + 8]);
    const float Dd = Dp[d];

    float h0 = 0.f, h1 = 0.f;

    __shared__ float sB[SCAN_TB][NST];
    __shared__ float sC[SCAN_TB][NST];

    for (int t0 = 0; t0 < TLEN; t0 += SCAN_TB) {
        __syncthreads();
        for (int i = tid; i < SCAN_TB * 32; i += 256) {
            const int r = i >> 5, cc = i & 31;
            const float v = g_proj[(size_t)(b * TLEN + t0 + r) * NPROJ + DTR + cc];
            if (cc < NST) sB[r][cc] = v;
            else sC[r][cc - NST] = v;
        }
        __syncthreads();

        for (int tt = 0; tt < SCAN_TB; ++tt) {
            const size_t row = (size_t)(b * TLEN + t0 + tt);
            const size_t idx = row * DI + d;
            const float delta = g_delta[idx];
            const float uc = g_uc[idx];
            const float du = delta * uc;

            h0 = __expf(delta * A0) * h0 + du * sB[tt][n];
            h1 = __expf(delta * A1) * h1 + du * sB[tt][n + 8];
            float y = h0 * sC[tt][n] + h1 * sC[tt][n + 8];
            y += __shfl_xor_sync(0xffffffffu, y, 1);
            y += __shfl_xor_sync(0xffffffffu, y, 2);
            y += __shfl_xor_sync(0xffffffffu, y, 4);

            if (n == 0) {
                const float z = g_uz[row * (2 * DI) + DI + d];
                const float gate = z / (1.f + __expf(-z));
                const float v = (y + uc * Dd) * gate;
                const __nv_bfloat16 h = __float2bfloat16(v);
                gy_h[idx] = h;
                gy_l[idx] = __float2bfloat16(v - __bfloat162float(h));
            }
        }
    }
}

// ---------------------------------------------------------------------------
extern "C" void kernel_launch(void* const* d_in, const int* in_sizes, int n_in,
                              void* d_out, int out_size)
{
    const float* x      = (const float*)d_in[0];
    const float* W_in   = (const float*)d_in[1];
    const float* conv_w = (const float*)d_in[2];
    const float* conv_b = (const float*)d_in[3];
    const float* W_xprj = (const float*)d_in[4];
    const float* W_dt   = (const float*)d_in[5];
    const float* b_dt   = (const float*)d_in[6];
    const float* A_log  = (const float*)d_in[7];
    const float* Dp     = (const float*)d_in[8];
    const float* W_out  = (const float*)d_in[9];
    float* out = (float*)d_out;

    cudaFuncSetAttribute(tgemm_mma<128>, cudaFuncAttributeMaxDynamicSharedMemorySize, TG_SMEM_BYTES);
    cudaFuncSetAttribute(tgemm_mma<96>,  cudaFuncAttributeMaxDynamicSharedMemorySize, TG_SMEM_BYTES);

    void *p_uz, *p_proj;
    void *p_xh, *p_xl, *p_WinTh, *p_WinTl, *p_uch, *p_ucl;
    void *p_WxTh, *p_WxTl, *p_yh, *p_yl, *p_WoTh, *p_WoTl;
    cudaGetSymbolAddress(&p_uz, g_uz);
    cudaGetSymbolAddress(&p_proj, g_proj);
    cudaGetSymbolAddress(&p_xh, gx_h);       cudaGetSymbolAddress(&p_xl, gx_l);
    cudaGetSymbolAddress(&p_WinTh, gWinT_h); cudaGetSymbolAddress(&p_WinTl, gWinT_l);
    cudaGetSymbolAddress(&p_uch, guc_h);     cudaGetSymbolAddress(&p_ucl, guc_l);
    cudaGetSymbolAddress(&p_WxTh, gWxT_h);   cudaGetSymbolAddress(&p_WxTl, gWxT_l);
    cudaGetSymbolAddress(&p_yh, gy_h);       cudaGetSymbolAddress(&p_yl, gy_l);
    cudaGetSymbolAddress(&p_WoTh, gWoT_h);   cudaGetSymbolAddress(&p_WoTl, gWoT_l);

    // --- operand preparation -------------------------------------------------
    {
        size_t n = (size_t)MROWS * DM;
        split_kernel<<<(unsigned)((n + 255) / 256), 256>>>(
            x, (__nv_bfloat16*)p_xh, (__nv_bfloat16*)p_xl, n);
    }
    tsplit_kernel<<<dim3((2 * DI) / 32, DM / 32), 1024>>>(
        W_in, (__nv_bfloat16*)p_WinTh, (__nv_bfloat16*)p_WinTl, DM, 2 * DI);
    tsplit_kernel<<<dim3(NPROJ / 32, DI / 32), 1024>>>(
        W_xprj, (__nv_bfloat16*)p_WxTh, (__nv_bfloat16*)p_WxTl, DI, NPROJ);
    tsplit_kernel<<<dim3(DM / 32, DI / 32), 1024>>>(
        W_out, (__nv_bfloat16*)p_WoTh, (__nv_bfloat16*)p_WoTl, DI, DM);

    // --- 1) xz = x @ W_in  (HMMA) -------------------------------------------
    tgemm_mma<128><<<dim3((2 * DI) / 128, MROWS / 128), 256, TG_SMEM_BYTES>>>(
        (const __nv_bfloat16*)p_xh, (const __nv_bfloat16*)p_xl,
        (const __nv_bfloat16*)p_WinTh, (const __nv_bfloat16*)p_WinTl,
        (float*)p_uz, DM, 2 * DI);

    // --- 2) conv + SiLU (+ fused bf16 split) --------------------------------
    {
        const size_t total = (size_t)MROWS * DI;
        conv_silu_kernel<<<(unsigned)((total + 255) / 256), 256>>>(conv_w, conv_b);
    }

    // --- 3) proj = uc @ W_xproj (HMMA) --------------------------------------
    tgemm_mma<96><<<dim3(1, MROWS / 128), 256, TG_SMEM_BYTES>>>(
        (const __nv_bfloat16*)p_uch, (const __nv_bfloat16*)p_ucl,
        (const __nv_bfloat16*)p_WxTh, (const __nv_bfloat16*)p_WxTl,
        (float*)p_proj, DI, NPROJ);

    // --- 4) delta ------------------------------------------------------------
    dt_softplus_kernel<<<dim3(DI / 256, MROWS / DT_TM), 256>>>(W_dt, b_dt);

    // --- 5) scan (+ fused bf16 split of gated y) -----------------------------
    scan_kernel<<<dim3(DI / 32, BSZ), 256>>>(A_log, Dp);

    // --- 6) out = y @ W_out (HMMA) ------------------------------------------
    tgemm_mma<128><<<dim3(DM / 128, MROWS / 128), 256, TG_SMEM_BYTES>>>(
        (const __nv_bfloat16*)p_yh, (const __nv_bfloat16*)p_yl,
        (const __nv_bfloat16*)p_WoTh, (const __nv_bfloat16*)p_WoTl,
        out, DI, DM);
}

// round 5
// speedup vs baseline: 4.3107x; 3.2221x over previous
#include <cuda_runtime.h>
#include <cuda_bf16.h>
#include <cstdint>
#include <math.h>

// Problem constants
#define BSZ   2
#define TLEN  2048
#define DM    1024
#define DI    2048
#define NST   16
#define DTR   64
#define NPROJ 96
#define MROWS (BSZ*TLEN)    // 4096
#define KSPLIT 8

// ---------------------------------------------------------------------------
// Scratch (device globals; allocation-free rule)
// ---------------------------------------------------------------------------
__device__ __align__(256) float g_uz[(size_t)MROWS * 2 * DI];   // u | z
__device__ __align__(256) float g_uc[(size_t)MROWS * DI];
__device__ __align__(256) float g_proj[(size_t)MROWS * NPROJ];
__device__ __align__(256) float g_projp[(size_t)KSPLIT * MROWS * NPROJ];
__device__ __align__(256) float g_delta[(size_t)MROWS * DI];

__device__ __align__(256) __nv_bfloat16 gx_h[(size_t)MROWS * DM];
__device__ __align__(256) __nv_bfloat16 gx_l[(size_t)MROWS * DM];
__device__ __align__(256) __nv_bfloat16 gWinT_h[(size_t)(2 * DI) * DM];
__device__ __align__(256) __nv_bfloat16 gWinT_l[(size_t)(2 * DI) * DM];
__device__ __align__(256) __nv_bfloat16 guc_h[(size_t)MROWS * DI];
__device__ __align__(256) __nv_bfloat16 guc_l[(size_t)MROWS * DI];
__device__ __align__(256) __nv_bfloat16 gWxT_h[(size_t)NPROJ * DI];
__device__ __align__(256) __nv_bfloat16 gWxT_l[(size_t)NPROJ * DI];
__device__ __align__(256) __nv_bfloat16 gy_h[(size_t)MROWS * DI];
__device__ __align__(256) __nv_bfloat16 gy_l[(size_t)MROWS * DI];
__device__ __align__(256) __nv_bfloat16 gWoT_h[(size_t)DM * DI];
__device__ __align__(256) __nv_bfloat16 gWoT_l[(size_t)DM * DI];

// ---------------------------------------------------------------------------
// PTX helpers (baseline features only; ptxas target is sm_103 w/o 'a')
// ---------------------------------------------------------------------------
__device__ __forceinline__ uint32_t smem_u32(const void* p) {
    uint32_t a;
    asm("{ .reg .u64 t; cvta.to.shared.u64 t, %1; cvt.u32.u64 %0, t; }"
        : "=r"(a) : "l"(p));
    return a;
}
__device__ __forceinline__ void cp_async16(uint32_t dst, const void* src) {
    asm volatile("cp.async.cg.shared.global [%0], [%1], 16;" :: "r"(dst), "l"(src));
}
#define CP_COMMIT() asm volatile("cp.async.commit_group;" ::: "memory")
#define CP_WAIT(n)  asm volatile("cp.async.wait_group %0;" :: "n"(n) : "memory")

__device__ __forceinline__ void ldmat_x4(uint32_t* r, uint32_t addr) {
    asm volatile("ldmatrix.sync.aligned.m8n8.x4.shared.b16 {%0,%1,%2,%3}, [%4];"
        : "=r"(r[0]), "=r"(r[1]), "=r"(r[2]), "=r"(r[3]) : "r"(addr));
}
__device__ __forceinline__ void mma16816(float* c, const uint32_t* a, const uint32_t* b) {
    asm volatile(
        "mma.sync.aligned.m16n8k16.row.col.f32.bf16.bf16.f32 "
        "{%0,%1,%2,%3}, {%4,%5,%6,%7}, {%8,%9}, {%0,%1,%2,%3};"
        : "+f"(c[0]), "+f"(c[1]), "+f"(c[2]), "+f"(c[3])
        : "r"(a[0]), "r"(a[1]), "r"(a[2]), "r"(a[3]), "r"(b[0]), "r"(b[1]));
}

// ---------------------------------------------------------------------------
// bf16 3-split HMMA GEMM:  C[M,N] = A[M,K] * B^T   (B stored [N,K] row-major)
// A = Ah+Al, B = Bh+Bl; AhBh + AlBh + AhBl accumulated in fp32.
// CTA tile 128 x BN, BK=32, 256 threads (8 warps: 4 M x 2 N),
// cp.async double-buffered, ldmatrix fragment loads, optional split-K via
// blockIdx.z (k_begin = z*nchunks*32, C += z*cslice).
// ---------------------------------------------------------------------------
#define BKP 40                             // padded K stride (bf16 elems)
#define TILE_BYTES (128 * BKP * 2)         // 10240 B
#define STAGE_BYTES (4 * TILE_BYTES)       // Ah|Al|Bh|Bl
#define TG_SMEM_BYTES (2 * STAGE_BYTES)    // 81920 B

__device__ __forceinline__ void tile_load(const __nv_bfloat16* __restrict__ src,
                                          int row0, int K, int k0,
                                          uint32_t sbase, int tid, int nrows) {
#pragma unroll
    for (int p = 0; p < 2; ++p) {
        const int idx = tid + p * 256;
        const int row = idx >> 2;
        const int seg = idx & 3;
        if (row < nrows)
            cp_async16(sbase + (uint32_t)(row * BKP + seg * 8) * 2,
                       src + (size_t)(row0 + row) * K + k0 + seg * 8);
    }
}

template <int BN>
__global__ __launch_bounds__(256, 2) void tgemm_mma(
    const __nv_bfloat16* __restrict__ Ah, const __nv_bfloat16* __restrict__ Al,
    const __nv_bfloat16* __restrict__ Bh, const __nv_bfloat16* __restrict__ Bl,
    float* __restrict__ C, int K, int ldc, int nchunks, size_t cslice)
{
    extern __shared__ __nv_bfloat16 sm[];
    const uint32_t smb = smem_u32(sm);
    const int tid = threadIdx.x;
    const int wid = tid >> 5, lane = tid & 31;
    const int wy = wid & 3, wx = wid >> 2;       // 4 (M) x 2 (N)
    const int g = lane >> 2, q2 = (lane & 3) * 2;
    const int m0 = blockIdx.y * 128;
    const int n0 = blockIdx.x * BN;
    const int kb = blockIdx.z * (nchunks << 5);
    C += (size_t)blockIdx.z * cslice;
    constexpr int WN = BN / 2;                   // 64 or 48
    constexpr int NI = WN / 8;                   // 8 or 6
    constexpr int BROWS = (BN < 128) ? BN : 128;

    // ldmatrix per-lane offsets (bytes, within an operand tile)
    const int laneA_row = (((lane >> 3) & 1) << 3) + (lane & 7);
    const int colA = ((lane >> 4) & 1) << 3;
    const int laneB_row = (((lane >> 4) & 1) << 3) + (lane & 7);
    const int colB = ((lane >> 3) & 1) << 3;
    const uint32_t offA = (uint32_t)(((wy * 32 + laneA_row) * BKP + colA) * 2);
    const uint32_t offB = (uint32_t)(((wx * WN + laneB_row) * BKP + colB) * 2);

    float acc[2][NI][4];
#pragma unroll
    for (int mi = 0; mi < 2; ++mi)
#pragma unroll
        for (int ni = 0; ni < NI; ++ni)
#pragma unroll
            for (int j = 0; j < 4; ++j) acc[mi][ni][j] = 0.f;

    // prologue
    {
        tile_load(Ah, m0, K, kb, smb,                  tid, 128);
        tile_load(Al, m0, K, kb, smb + TILE_BYTES,     tid, 128);
        tile_load(Bh, n0, K, kb, smb + 2 * TILE_BYTES, tid, BROWS);
        tile_load(Bl, n0, K, kb, smb + 3 * TILE_BYTES, tid, BROWS);
        CP_COMMIT();
    }

    for (int c = 0; c < nchunks; ++c) {
        const int s = c & 1;
        if (c + 1 < nchunks) {
            const int k0 = kb + ((c + 1) << 5);
            const uint32_t sb = smb + (uint32_t)(s ^ 1) * STAGE_BYTES;
            tile_load(Ah, m0, K, k0, sb,                  tid, 128);
            tile_load(Al, m0, K, k0, sb + TILE_BYTES,     tid, 128);
            tile_load(Bh, n0, K, k0, sb + 2 * TILE_BYTES, tid, BROWS);
            tile_load(Bl, n0, K, k0, sb + 3 * TILE_BYTES, tid, BROWS);
            CP_COMMIT();
            CP_WAIT(1);
        } else {
            CP_WAIT(0);
        }
        __syncthreads();

        const uint32_t sb = smb + (uint32_t)s * STAGE_BYTES;
        const uint32_t sAh = sb, sAl = sb + TILE_BYTES;
        const uint32_t sBh = sb + 2 * TILE_BYTES, sBl = sb + 3 * TILE_BYTES;

#pragma unroll
        for (int kk = 0; kk < 2; ++kk) {
            const uint32_t kbyte = (uint32_t)(kk * 32);
            uint32_t ah[2][4], al[2][4];
#pragma unroll
            for (int mi = 0; mi < 2; ++mi) {
                const uint32_t mo = (uint32_t)(mi * 16 * BKP * 2);
                ldmat_x4(ah[mi], sAh + offA + mo + kbyte);
                ldmat_x4(al[mi], sAl + offA + mo + kbyte);
            }
#pragma unroll
            for (int nip = 0; nip < NI / 2; ++nip) {
                const uint32_t no = (uint32_t)(nip * 16 * BKP * 2);
                uint32_t bh[4], bl[4];
                ldmat_x4(bh, sBh + offB + no + kbyte);
                ldmat_x4(bl, sBl + offB + no + kbyte);
#pragma unroll
                for (int mi = 0; mi < 2; ++mi) {
                    mma16816(acc[mi][2 * nip],     ah[mi], bh);
                    mma16816(acc[mi][2 * nip],     al[mi], bh);
                    mma16816(acc[mi][2 * nip],     ah[mi], bl);
                    mma16816(acc[mi][2 * nip + 1], ah[mi], bh + 2);
                    mma16816(acc[mi][2 * nip + 1], al[mi], bh + 2);
                    mma16816(acc[mi][2 * nip + 1], ah[mi], bl + 2);
                }
            }
        }
        __syncthreads();
    }

    // epilogue
#pragma unroll
    for (int mi = 0; mi < 2; ++mi) {
        const int row = m0 + wy * 32 + mi * 16 + g;
#pragma unroll
        for (int ni = 0; ni < NI; ++ni) {
            const int col = n0 + wx * WN + ni * 8 + q2;
            *(float2*)&C[(size_t)row * ldc + col] =
                make_float2(acc[mi][ni][0], acc[mi][ni][1]);
            *(float2*)&C[(size_t)(row + 8) * ldc + col] =
                make_float2(acc[mi][ni][2], acc[mi][ni][3]);
        }
    }
}

// ---------------------------------------------------------------------------
// reduce split-K partials: g_proj = sum_z g_projp[z]
// ---------------------------------------------------------------------------
__global__ void reduce_proj_kernel() {
    const size_t i = (size_t)blockIdx.x * blockDim.x + threadIdx.x;
    if (i >= (size_t)MROWS * NPROJ) return;
    float s = 0.f;
#pragma unroll
    for (int z = 0; z < KSPLIT; ++z)
        s += g_projp[(size_t)z * MROWS * NPROJ + i];
    g_proj[i] = s;
}

// ---------------------------------------------------------------------------
// fp32 -> bf16 hi/lo split
// ---------------------------------------------------------------------------
__global__ void split_kernel(const float* __restrict__ src,
                             __nv_bfloat16* __restrict__ hi,
                             __nv_bfloat16* __restrict__ lo, size_t n)
{
    size_t i = (size_t)blockIdx.x * blockDim.x + threadIdx.x;
    if (i >= n) return;
    float v = src[i];
    __nv_bfloat16 h = __float2bfloat16(v);
    hi[i] = h;
    lo[i] = __float2bfloat16(v - __bfloat162float(h));
}

// ---------------------------------------------------------------------------
// transpose + split: src [K][N] fp32 -> hi/lo [N][K] bf16  (K,N mult of 32)
// ---------------------------------------------------------------------------
__global__ __launch_bounds__(1024) void tsplit_kernel(
    const float* __restrict__ src, __nv_bfloat16* __restrict__ hi,
    __nv_bfloat16* __restrict__ lo, int K, int N)
{
    __shared__ float tile[32][33];
    const int n0 = blockIdx.x * 32, k0 = blockIdx.y * 32;
    const int tx = threadIdx.x & 31, ty = threadIdx.x >> 5;
    tile[ty][tx] = src[(size_t)(k0 + ty) * N + n0 + tx];
    __syncthreads();
    const int k = k0 + tx, n = n0 + ty;
    float v = tile[tx][ty];
    __nv_bfloat16 h = __float2bfloat16(v);
    hi[(size_t)n * K + k] = h;
    lo[(size_t)n * K + k] = __float2bfloat16(v - __bfloat162float(h));
}

// ---------------------------------------------------------------------------
// Causal depthwise conv1d (k=4) + SiLU; writes fp32 uc and bf16 hi/lo
// ---------------------------------------------------------------------------
__global__ void conv_silu_kernel(const float* __restrict__ cw,
                                 const float* __restrict__ cb)
{
    const size_t idx = (size_t)blockIdx.x * blockDim.x + threadIdx.x;
    if (idx >= (size_t)MROWS * DI) return;
    const int d = (int)(idx % DI);
    const int m = (int)(idx / DI);
    const int t = m % TLEN;

    float acc = cb[d];
#pragma unroll
    for (int k = 0; k < 4; k++) {
        const int tt = t - 3 + k;
        if (tt >= 0)
            acc += g_uz[(size_t)(m - 3 + k) * (2 * DI) + d] * cw[d * 4 + k];
    }
    const float v = acc / (1.f + __expf(-acc));
    g_uc[idx] = v;
    const __nv_bfloat16 h = __float2bfloat16(v);
    guc_h[idx] = h;
    guc_l[idx] = __float2bfloat16(v - __bfloat162float(h));
}

// ---------------------------------------------------------------------------
// delta = softplus(proj[:, :64] @ W_dt + b_dt)
// ---------------------------------------------------------------------------
#define DT_TM 8
__global__ __launch_bounds__(256) void dt_softplus_kernel(
    const float* __restrict__ W_dt, const float* __restrict__ b_dt)
{
    __shared__ float sp[DT_TM][DTR];
    const int m0 = blockIdx.y * DT_TM;
    const int d = blockIdx.x * 256 + threadIdx.x;

    for (int i = threadIdx.x; i < DT_TM * DTR; i += 256)
        sp[i / DTR][i % DTR] = g_proj[(size_t)(m0 + i / DTR) * NPROJ + (i % DTR)];
    __syncthreads();

    const float bb = b_dt[d];
    float acc[DT_TM];
#pragma unroll
    for (int i = 0; i < DT_TM; i++) acc[i] = bb;

#pragma unroll 8
    for (int r = 0; r < DTR; r++) {
        const float w = W_dt[(size_t)r * DI + d];
#pragma unroll
        for (int i = 0; i < DT_TM; i++) acc[i] += sp[i][r] * w;
    }
#pragma unroll
    for (int i = 0; i < DT_TM; i++) {
        const float x = acc[i];
        g_delta[(size_t)(m0 + i) * DI + d] =
            fmaxf(x, 0.f) + log1pf(__expf(-fabsf(x)));
    }
}

// ---------------------------------------------------------------------------
// SSM scan, smem-tiled. Block = 256 threads = 32 d-channels x 8 state-lanes.
// All per-step inputs staged coalesced into smem in 64-step chunks; gated
// output + bf16 split written coalesced in an epilogue phase.
// ---------------------------------------------------------------------------
#define SCAN_TB 64
__global__ __launch_bounds__(256) void scan_kernel(
    const float* __restrict__ A_log, const float* __restrict__ Dp)
{
    const int b = blockIdx.y;
    const int tid = threadIdx.x;
    const int warp = tid >> 5;
    const int lane = tid & 31;
    const int d_sub = lane >> 3;
    const int n = lane & 7;
    const int d_local = warp * 4 + d_sub;
    const int d0 = blockIdx.x * 32;
    const int d = d0 + d_local;

    __shared__ float sDelta[SCAN_TB][33];
    __shared__ float sUc[SCAN_TB][33];
    __shared__ float sZ[SCAN_TB][33];
    __shared__ float sY[SCAN_TB][33];
    __shared__ float sB[SCAN_TB][NST];
    __shared__ float sC[SCAN_TB][NST];
    __shared__ float sD[32];

    if (tid < 32) sD[tid] = Dp[d0 + tid];

    const float A0 = -__expf(A_log[(size_t)d * NST + n]);
    const float A1 = -__expf(A_log[(size_t)d * NST + n + 8]);

    float h0 = 0.f, h1 = 0.f;

    for (int t0 = 0; t0 < TLEN; t0 += SCAN_TB) {
        __syncthreads();
        // coalesced stage-in
#pragma unroll
        for (int p = 0; p < 8; ++p) {
            const int i = tid + p * 256;
            const int r = i >> 5, c = i & 31;
            const size_t row = (size_t)(b * TLEN + t0 + r);
            sDelta[r][c] = g_delta[row * DI + d0 + c];
            sUc[r][c]    = g_uc[row * DI + d0 + c];
            sZ[r][c]     = g_uz[row * (2 * DI) + DI + d0 + c];
            const float v = g_proj[row * NPROJ + DTR + c];
            if (c < NST) sB[r][c] = v;
            else         sC[r][c - NST] = v;
        }
        __syncthreads();

#pragma unroll 4
        for (int tt = 0; tt < SCAN_TB; ++tt) {
            const float delta = sDelta[tt][d_local];
            const float du = delta * sUc[tt][d_local];
            h0 = __expf(delta * A0) * h0 + du * sB[tt][n];
            h1 = __expf(delta * A1) * h1 + du * sB[tt][n + 8];
            float y = h0 * sC[tt][n] + h1 * sC[tt][n + 8];
            y += __shfl_xor_sync(0xffffffffu, y, 1);
            y += __shfl_xor_sync(0xffffffffu, y, 2);
            y += __shfl_xor_sync(0xffffffffu, y, 4);
            if (n == 0) sY[tt][d_local] = y;
        }
        __syncthreads();

        // coalesced epilogue: gate + skip + bf16 split
#pragma unroll
        for (int p = 0; p < 8; ++p) {
            const int i = tid + p * 256;
            const int r = i >> 5, c = i & 31;
            const float uc = sUc[r][c];
            const float z = sZ[r][c];
            const float gate = z / (1.f + __expf(-z));
            const float v = (sY[r][c] + uc * sD[c]) * gate;
            const size_t idx = (size_t)(b * TLEN + t0 + r) * DI + d0 + c;
            const __nv_bfloat16 h = __float2bfloat16(v);
            gy_h[idx] = h;
            gy_l[idx] = __float2bfloat16(v - __bfloat162float(h));
        }
    }
}

// ---------------------------------------------------------------------------
extern "C" void kernel_launch(void* const* d_in, const int* in_sizes, int n_in,
                              void* d_out, int out_size)
{
    const float* x      = (const float*)d_in[0];
    const float* W_in   = (const float*)d_in[1];
    const float* conv_w = (const float*)d_in[2];
    const float* conv_b = (const float*)d_in[3];
    const float* W_xprj = (const float*)d_in[4];
    const float* W_dt   = (const float*)d_in[5];
    const float* b_dt   = (const float*)d_in[6];
    const float* A_log  = (const float*)d_in[7];
    const float* Dp     = (const float*)d_in[8];
    const float* W_out  = (const float*)d_in[9];
    float* out = (float*)d_out;

    cudaFuncSetAttribute(tgemm_mma<128>, cudaFuncAttributeMaxDynamicSharedMemorySize, TG_SMEM_BYTES);
    cudaFuncSetAttribute(tgemm_mma<96>,  cudaFuncAttributeMaxDynamicSharedMemorySize, TG_SMEM_BYTES);

    void *p_uz, *p_projp;
    void *p_xh, *p_xl, *p_WinTh, *p_WinTl, *p_uch, *p_ucl;
    void *p_WxTh, *p_WxTl, *p_yh, *p_yl, *p_WoTh, *p_WoTl;
    cudaGetSymbolAddress(&p_uz, g_uz);
    cudaGetSymbolAddress(&p_projp, g_projp);
    cudaGetSymbolAddress(&p_xh, gx_h);       cudaGetSymbolAddress(&p_xl, gx_l);
    cudaGetSymbolAddress(&p_WinTh, gWinT_h); cudaGetSymbolAddress(&p_WinTl, gWinT_l);
    cudaGetSymbolAddress(&p_uch, guc_h);     cudaGetSymbolAddress(&p_ucl, guc_l);
    cudaGetSymbolAddress(&p_WxTh, gWxT_h);   cudaGetSymbolAddress(&p_WxTl, gWxT_l);
    cudaGetSymbolAddress(&p_yh, gy_h);       cudaGetSymbolAddress(&p_yl, gy_l);
    cudaGetSymbolAddress(&p_WoTh, gWoT_h);   cudaGetSymbolAddress(&p_WoTl, gWoT_l);

    // operand prep
    {
        size_t n = (size_t)MROWS * DM;
        split_kernel<<<(unsigned)((n + 255) / 256), 256>>>(
            x, (__nv_bfloat16*)p_xh, (__nv_bfloat16*)p_xl, n);
    }
    tsplit_kernel<<<dim3((2 * DI) / 32, DM / 32), 1024>>>(
        W_in, (__nv_bfloat16*)p_WinTh, (__nv_bfloat16*)p_WinTl, DM, 2 * DI);
    tsplit_kernel<<<dim3(NPROJ / 32, DI / 32), 1024>>>(
        W_xprj, (__nv_bfloat16*)p_WxTh, (__nv_bfloat16*)p_WxTl, DI, NPROJ);
    tsplit_kernel<<<dim3(DM / 32, DI / 32), 1024>>>(
        W_out, (__nv_bfloat16*)p_WoTh, (__nv_bfloat16*)p_WoTl, DI, DM);

    // 1) xz = x @ W_in
    tgemm_mma<128><<<dim3((2 * DI) / 128, MROWS / 128, 1), 256, TG_SMEM_BYTES>>>(
        (const __nv_bfloat16*)p_xh, (const __nv_bfloat16*)p_xl,
        (const __nv_bfloat16*)p_WinTh, (const __nv_bfloat16*)p_WinTl,
        (float*)p_uz, DM, 2 * DI, DM / 32, 0);

    // 2) conv + SiLU (+ bf16 split)
    {
        const size_t total = (size_t)MROWS * DI;
        conv_silu_kernel<<<(unsigned)((total + 255) / 256), 256>>>(conv_w, conv_b);
    }

    // 3) proj = uc @ W_xproj, split-K=8 -> partials -> reduce
    tgemm_mma<96><<<dim3(1, MROWS / 128, KSPLIT), 256, TG_SMEM_BYTES>>>(
        (const __nv_bfloat16*)p_uch, (const __nv_bfloat16*)p_ucl,
        (const __nv_bfloat16*)p_WxTh, (const __nv_bfloat16*)p_WxTl,
        (float*)p_projp, DI, NPROJ, (DI / KSPLIT) / 32,
        (size_t)MROWS * NPROJ);
    {
        const size_t total = (size_t)MROWS * NPROJ;
        reduce_proj_kernel<<<(unsigned)((total + 255) / 256), 256>>>();
    }

    // 4) delta
    dt_softplus_kernel<<<dim3(DI / 256, MROWS / DT_TM), 256>>>(W_dt, b_dt);

    // 5) scan
    scan_kernel<<<dim3(DI / 32, BSZ), 256>>>(A_log, Dp);

    // 6) out = y @ W_out
    tgemm_mma<128><<<dim3(DM / 128, MROWS / 128, 1), 256, TG_SMEM_BYTES>>>(
        (const __nv_bfloat16*)p_yh, (const __nv_bfloat16*)p_yl,
        (const __nv_bfloat16*)p_WoTh, (const __nv_bfloat16*)p_WoTl,
        out, DI, DM, DI / 32, 0);
}